// round 15
// baseline (speedup 1.0000x reference)
#include <cuda_runtime.h>
#include <cuda_bf16.h>
#include <cuda_fp16.h>
#include <math.h>
#include <cstdint>

// Problem constants
#define B   4
#define C   256
#define H   64
#define W   64
#define O   256
#define K   9           // 3x3
#define HW  4096        // H*W
#define CK  2304        // C*K
#define NPIX 16384      // B*H*W

// main GEMM config (1-pass fp16, 128 threads, warp tile 64x64, occ 2)
#define KC      64
#define NCHUNK  36      // 2304/64
#define STG     3
#define STAGE_BYTES 32768   // A 16KB + B 16KB
#define SMEM_DYN (1024 + STG * STAGE_BYTES)

// offset-conv GEMM config
#define NCH2    36      // 9 taps x 4 chunks of 64ch
#define STG2    4
#define STAGE2  20480   // A 4KB + B 16KB
#define SMEM2   (1024 + STG2 * STAGE2)

// ---------------- scratch (__device__ globals; no allocs allowed) -------------
__device__ float  g_om[B * 27 * HW];              // offset-conv output
__device__ __half g_xhalf[(size_t)NPIX * C];      // x in NHWC fp16 (offconv B + gather)
__device__ __half g_womh[32 * CK];                // w_om k-major fp16, rows 27..31 = 0
__device__ __half g_whalf[O * CK];                // weight k-major fp16
__device__ __half g_cols[(size_t)NPIX * CK];      // im2col cols fp16
__device__ __half g_zero[64];                     // zero-initialized OOB source

// ---------------- PTX helpers -------------------------------------------------
__device__ __forceinline__ uint32_t smem_u32(const void* p) {
    uint32_t a;
    asm("{ .reg .u64 t; cvta.to.shared.u64 t, %1; cvt.u32.u64 %0, t; }" : "=r"(a) : "l"(p));
    return a;
}
__device__ __forceinline__ void cp16(uint32_t dst, const void* src) {
    asm volatile("cp.async.cg.shared.global [%0], [%1], 16;" :: "r"(dst), "l"(src) : "memory");
}
#define CP_COMMIT() asm volatile("cp.async.commit_group;" ::: "memory")
#define CP_WAIT1()  asm volatile("cp.async.wait_group 1;" ::: "memory")
#define CP_WAIT2()  asm volatile("cp.async.wait_group 2;" ::: "memory")
#define CP_WAIT0()  asm volatile("cp.async.wait_group 0;" ::: "memory")

__device__ __forceinline__ uint32_t sw128(uint32_t off) { return off ^ ((off >> 3) & 0x70); }

__device__ __forceinline__ void ldsm_x4(uint32_t* r, uint32_t addr) {
    asm volatile("ldmatrix.sync.aligned.m8n8.x4.shared.b16 {%0,%1,%2,%3}, [%4];"
        : "=r"(r[0]), "=r"(r[1]), "=r"(r[2]), "=r"(r[3]) : "r"(addr));
}
__device__ __forceinline__ void mma16816(float* d, const uint32_t* a, const uint32_t* b) {
    asm volatile("mma.sync.aligned.m16n8k16.row.col.f32.f16.f16.f32 "
        "{%0,%1,%2,%3}, {%4,%5,%6,%7}, {%8,%9}, {%0,%1,%2,%3};"
        : "+f"(d[0]), "+f"(d[1]), "+f"(d[2]), "+f"(d[3])
        : "r"(a[0]), "r"(a[1]), "r"(a[2]), "r"(a[3]), "r"(b[0]), "r"(b[1]));
}

// ---------------- kernel 1: prep (transpose + wsplit + womprep) ----------------
// grid 4960 x 256 threads:
//   [0, 4096)    : NCHW->NHWC transpose (fp16 only)
//   [4096, 4672) : wsplit -> fp16 k-major
//   [4672, 4960) : w_om -> fp16 k-major padded to 32 rows
__global__ void __launch_bounds__(256) prep_kernel(const float* __restrict__ x,
                                                   const float* __restrict__ w_om,
                                                   const float* __restrict__ weight) {
    const int bid = blockIdx.x;
    const int tid = threadIdx.x;

    if (bid < 4096) {
        __shared__ float t[32][33];
        const int hw0 = (bid & 127) << 5;
        const int c0  = ((bid >> 7) & 7) << 5;
        const int b   = bid >> 10;
        const int tx = tid & 31, ty = tid >> 5;
        #pragma unroll
        for (int j = 0; j < 4; ++j) {
            int c = c0 + ty + 8 * j;
            t[ty + 8 * j][tx] = x[(((b << 8) + c) << 12) + hw0 + tx];
        }
        __syncthreads();
        #pragma unroll
        for (int j = 0; j < 4; ++j) {
            int hw = hw0 + ty + 8 * j;
            g_xhalf[(size_t)(((b << 12) + hw) << 8) + c0 + tx] =
                __float2half_rn(t[tx][ty + 8 * j]);
        }
    } else if (bid < 4672) {
        // ---- wsplit: fp16, k-major ----
        int i = (bid - 4096) * 1024 + tid * 4;  // < 589824
        const float4 v4 = *reinterpret_cast<const float4*>(weight + i);
        const float vs[4] = { v4.x, v4.y, v4.z, v4.w };
        #pragma unroll
        for (int q = 0; q < 4; ++q) {
            int e = i + q;
            int o = e / CK, r = e - o * CK;
            int c = r / 9, k = r - c * 9;
            g_whalf[o * CK + k * 256 + c] = __float2half_rn(vs[q]);
        }
    } else {
        // ---- womprep: womh[o][k*256+c] = w_om[o*2304 + c*9 + k], o<27 else 0 ----
        int i = (bid - 4672) * 256 + tid;       // < 73728 exactly
        int o = i / CK, r = i - o * CK;
        int k = r >> 8, c = r & 255;
        g_womh[i] = (o < 27) ? __float2half_rn(w_om[o * CK + c * 9 + k]) : __half(0.0f);
    }
}

// ---------------- kernel 2: offset-conv HMMA GEMM ------------------------------
// om[27, px] = w_om[27 x 2304] x im2col(x)[2304 x px].  B rows built on the fly
// from fp16 NHWC x: tap row = contiguous 64-ch chunk at shifted pixel (or zeros).
// grid 128 (one 128-px tile each), 256 threads (8 warps); warp tile 32(m) x 16(n).
__global__ void __launch_bounds__(256, 1)
offconv_kernel() {
    extern __shared__ __align__(16) char dyn_smem[];
    __shared__ int spx[K][128];                    // per-(tap, px) element offset or -1

    const uint32_t smem_base = smem_u32(dyn_smem);
    const uint32_t tile0 = (smem_base + 1023u) & ~1023u;

    const int tid  = threadIdx.x;
    const int wid  = tid >> 5;
    const int lane = tid & 31;
    const int pxb  = blockIdx.x << 7;              // 128 px per CTA
    const int b    = pxb >> 12;
    const int hwb  = pxb & 4095;

    // precompute per-px per-tap source offsets
    for (int i = tid; i < K * 128; i += 256) {
        int k = i >> 7, p = i & 127;
        int hw = hwb + p;
        int h = hw >> 6, w = hw & 63;
        int ky = k / 3 - 1, kx = k - (ky + 1) * 3 - 1;
        bool valid = ((unsigned)(h + ky) < H) && ((unsigned)(w + kx) < W);
        spx[k][p] = valid ? (((b << 12) + hw + ky * 64 + kx) << 8) : -1;
    }
    __syncthreads();

    const int rA = tid >> 3;      // 0..31
    const int sg = tid & 7;

    auto load_chunk = [&](int j) {
        int st = j % STG2;
        uint32_t sa = tile0 + st * STAGE2;         // A: 32 x 128B = 4KB
        uint32_t sb = sa + 4096;                   // B: 128 x 128B = 16KB
        int k  = j >> 2;
        int c0 = (j & 3) << 6;
        cp16(sa + sw128((uint32_t)(rA * 128 + sg * 16)), g_womh + rA * CK + k * 256 + c0 + sg * 8);
        #pragma unroll
        for (int q = 0; q < 4; ++q) {
            int idx = tid + (q << 8);
            int row = idx >> 3, s2 = idx & 7;
            int off = spx[k][row];
            const __half* src = (off >= 0) ? (g_xhalf + off + c0 + s2 * 8) : (g_zero + s2 * 8);
            cp16(sb + sw128((uint32_t)(row * 128 + s2 * 16)), src);
        }
        CP_COMMIT();
    };

    float acc[2][2][4];
    #pragma unroll
    for (int i = 0; i < 2; ++i)
        #pragma unroll
        for (int j = 0; j < 2; ++j)
            #pragma unroll
            for (int q = 0; q < 4; ++q) acc[i][j][q] = 0.0f;

    const uint32_t aRow = (uint32_t)(lane & 15);
    const uint32_t aCb  = (uint32_t)((lane >> 4) << 4);
    const uint32_t bRow = (uint32_t)(wid * 16 + ((lane >> 4) << 3) + (lane & 7));
    const uint32_t bCb  = (uint32_t)(((lane >> 3) & 1) << 4);

    load_chunk(0);
    load_chunk(1);
    load_chunk(2);

    for (int i = 0; i < NCH2; ++i) {
        CP_WAIT2();
        __syncthreads();
        if (i + STG2 - 1 < NCH2) load_chunk(i + STG2 - 1);

        int st = i % STG2;
        uint32_t sa = tile0 + st * STAGE2;
        uint32_t sb = sa + 4096;

        #pragma unroll
        for (int kk = 0; kk < 4; ++kk) {
            uint32_t a[2][4], bfr[2][2];
            #pragma unroll
            for (int mf = 0; mf < 2; ++mf)
                ldsm_x4(a[mf], sa + sw128((aRow + mf * 16) * 128 + aCb + kk * 32));
            {
                uint32_t r[4];
                ldsm_x4(r, sb + sw128(bRow * 128 + bCb + kk * 32));
                bfr[0][0] = r[0]; bfr[0][1] = r[1];
                bfr[1][0] = r[2]; bfr[1][1] = r[3];
            }
            #pragma unroll
            for (int mf = 0; mf < 2; ++mf)
                #pragma unroll
                for (int nf = 0; nf < 2; ++nf)
                    mma16816(acc[mf][nf], a[mf], bfr[nf]);
        }
    }
    CP_WAIT0();

    // epilogue: D[m=o][n=px] -> g_om[b][o][hw]
    const int nBase = hwb + wid * 16 + (lane & 3) * 2;
    #pragma unroll
    for (int mf = 0; mf < 2; ++mf) {
        int o0 = mf * 16 + (lane >> 2);
        int o8 = o0 + 8;
        #pragma unroll
        for (int nf = 0; nf < 2; ++nf) {
            int n = nBase + nf * 8;
            if (o0 < 27)
                *reinterpret_cast<float2*>(g_om + (b * 27 + o0) * HW + n) =
                    make_float2(acc[mf][nf][0], acc[mf][nf][1]);
            if (o8 < 27)
                *reinterpret_cast<float2*>(g_om + (b * 27 + o8) * HW + n) =
                    make_float2(acc[mf][nf][2], acc[mf][nf][3]);
        }
    }
}

// ---------------- kernel 3: fused params + gather (fp16 corner loads) ----------
// grid 2048, block 256 = 8 px. Phase 1: 72 threads compute the 8x9 sampling
// params into smem. Phase 2: warp = one pixel, lane = 4 channels (uint2 in/out).
__global__ void __launch_bounds__(256) gather_kernel(const float* __restrict__ b_om) {
    __shared__ float4 s_ww[8][9];
    __shared__ int4   s_cc[8][9];

    const int tid  = threadIdx.x;
    const int pix0 = blockIdx.x << 3;
    const int b    = pix0 >> 12;

    if (tid < 72) {
        const int p = tid / 9;
        const int k = tid - p * 9;
        const int hw = (pix0 + p) & 4095;
        const int h  = hw >> 6;
        const int w  = hw & 63;
        const float* omb = g_om + b * 27 * HW + hw;

        float off_y = omb[(2 * k    ) * HW] + b_om[2 * k];
        float off_x = omb[(2 * k + 1) * HW] + b_om[2 * k + 1];
        float mval  = omb[(18 + k   ) * HW] + b_om[18 + k];
        float m = 1.0f / (1.0f + expf(-mval));

        float py = (float)(h - 1 + k / 3) + off_y;
        float px = (float)(w - 1 + k % 3) + off_x;

        float y0f = floorf(py), x0f = floorf(px);
        float ly = py - y0f, lx = px - x0f;
        int y0 = (int)y0f, x0 = (int)x0f;
        int y1 = y0 + 1,   x1 = x0 + 1;

        float vy0 = (y0 >= 0 && y0 < H) ? 1.0f : 0.0f;
        float vy1 = (y1 >= 0 && y1 < H) ? 1.0f : 0.0f;
        float vx0 = (x0 >= 0 && x0 < W) ? 1.0f : 0.0f;
        float vx1 = (x1 >= 0 && x1 < W) ? 1.0f : 0.0f;

        float4 wv;
        wv.x = (1.0f - ly) * (1.0f - lx) * m * vy0 * vx0;
        wv.y = (1.0f - ly) * lx          * m * vy0 * vx1;
        wv.z = ly * (1.0f - lx)          * m * vy1 * vx0;
        wv.w = ly * lx                   * m * vy1 * vx1;

        int4 cv;
        cv.x = min(max(y0, 0), H - 1) * W;
        cv.y = min(max(y1, 0), H - 1) * W;
        cv.z = min(max(x0, 0), W - 1);
        cv.w = min(max(x1, 0), W - 1);

        s_ww[p][k] = wv;
        s_cc[p][k] = cv;
    }
    __syncthreads();

    const int wid  = tid >> 5;
    const int lane = tid & 31;
    const int px   = pix0 + wid;

    // fp16 corners: uint2 = 4 halves; pixel stride = 256 halves = 64 uint2
    const uint2* xb = reinterpret_cast<const uint2*>(g_xhalf) + ((size_t)b << 18);
    uint2* outp = reinterpret_cast<uint2*>(g_cols + (size_t)px * CK);

    #pragma unroll
    for (int k = 0; k < K; ++k) {
        const float4 ww = s_ww[wid][k];
        const int4   cc = s_cc[wid][k];
        const int p00 = (cc.x + cc.z) << 6;
        const int p01 = (cc.x + cc.w) << 6;
        const int p10 = (cc.y + cc.z) << 6;
        const int p11 = (cc.y + cc.w) << 6;
        #pragma unroll
        for (int it = 0; it < 2; ++it) {
            const int c4 = (it << 5) + lane;   // uint2 index: channels 4*c4..4*c4+3
            uint2 u00 = xb[p00 + c4], u01 = xb[p01 + c4];
            uint2 u10 = xb[p10 + c4], u11 = xb[p11 + c4];
            float2 f00a = __half22float2(*reinterpret_cast<__half2*>(&u00.x));
            float2 f00b = __half22float2(*reinterpret_cast<__half2*>(&u00.y));
            float2 f01a = __half22float2(*reinterpret_cast<__half2*>(&u01.x));
            float2 f01b = __half22float2(*reinterpret_cast<__half2*>(&u01.y));
            float2 f10a = __half22float2(*reinterpret_cast<__half2*>(&u10.x));
            float2 f10b = __half22float2(*reinterpret_cast<__half2*>(&u10.y));
            float2 f11a = __half22float2(*reinterpret_cast<__half2*>(&u11.x));
            float2 f11b = __half22float2(*reinterpret_cast<__half2*>(&u11.y));
            float va = ww.x * f00a.x + ww.y * f01a.x + ww.z * f10a.x + ww.w * f11a.x;
            float vb = ww.x * f00a.y + ww.y * f01a.y + ww.z * f10a.y + ww.w * f11a.y;
            float vc = ww.x * f00b.x + ww.y * f01b.x + ww.z * f10b.x + ww.w * f11b.x;
            float vd = ww.x * f00b.y + ww.y * f01b.y + ww.z * f10b.y + ww.w * f11b.y;
            __half2 h2a = __floats2half2_rn(va, vb);
            __half2 h2b = __floats2half2_rn(vc, vd);
            uint2 st;
            st.x = *reinterpret_cast<uint32_t*>(&h2a);
            st.y = *reinterpret_cast<uint32_t*>(&h2b);
            outp[k * 64 + c4] = st;
        }
    }
}

// ---------------- kernel 4: HMMA GEMM  D[o, px] = Whalf x Cols^T ---------------
// grid (2, 128): tile 128(o) x 128(px), 128 threads (4 warps as 2m x 2n), occ 2.
// Warp tile 64 x 64: smem reads/chunk = A 16KB x2 + B 16KB x2 = 64KB (amp 2)
// vs 96KB at warp-64x32 -> crossbar off the critical path; regs ~190 (<=256 @occ2)
// leave ptxas room to software-pipeline LDSM.
__global__ void __launch_bounds__(128, 2)
gemm_kernel(const float* __restrict__ bias, float* __restrict__ out) {
    extern __shared__ __align__(16) char dyn_smem[];
    const uint32_t smem_base = smem_u32(dyn_smem);
    const uint32_t tile0 = (smem_base + 1023u) & ~1023u;

    const int tid  = threadIdx.x;
    const int wid  = tid >> 5;
    const int lane = tid & 31;
    const int o_tile = blockIdx.x;            // 0..1 (fast dim: same-px pair adjacent)
    const int pxb    = blockIdx.y << 7;       // 128 px per CTA

    const int wm = wid & 1;                   // m offset 64*wm
    const int wn = wid >> 1;                  // n offset 64*wn

    const __half* wA = g_whalf + (size_t)o_tile * 128 * CK;
    const __half* cB = g_cols + (size_t)pxb * CK;

    const int r0 = tid >> 3;                  // 0..15
    const int sg = tid & 7;

    auto load_chunk = [&](int j) {
        int st = j % STG;
        uint32_t sa = tile0 + st * STAGE_BYTES;
        uint32_t sb = sa + 16384;
        int koff = j * KC + sg * 8;
        #pragma unroll
        for (int q = 0; q < 8; ++q) {        // A: 128 rows, 1024 segs / 128 thr
            int r = r0 + (q << 4);
            cp16(sa + sw128((uint32_t)(r * 128 + sg * 16)), wA + (size_t)r * CK + koff);
        }
        #pragma unroll
        for (int q = 0; q < 8; ++q) {        // B: 128 rows
            int r = r0 + (q << 4);
            cp16(sb + sw128((uint32_t)(r * 128 + sg * 16)), cB + (size_t)r * CK + koff);
        }
        CP_COMMIT();
    };

    float acc[4][8][4];
    #pragma unroll
    for (int i = 0; i < 4; ++i)
        #pragma unroll
        for (int j = 0; j < 8; ++j)
            #pragma unroll
            for (int q = 0; q < 4; ++q) acc[i][j][q] = 0.0f;

    const uint32_t aRow = (uint32_t)(wm * 64 + (lane & 15));
    const uint32_t aCb  = (uint32_t)((lane >> 4) << 4);
    const uint32_t bRow = (uint32_t)(wn * 64 + ((lane >> 4) << 3) + (lane & 7));
    const uint32_t bCb  = (uint32_t)(((lane >> 3) & 1) << 4);

    load_chunk(0);
    load_chunk(1);

    for (int i = 0; i < NCHUNK; ++i) {
        if (i + 1 < NCHUNK) CP_WAIT1(); else CP_WAIT0();
        __syncthreads();
        if (i + STG - 1 < NCHUNK) load_chunk(i + STG - 1);

        int st = i % STG;
        uint32_t sa = tile0 + st * STAGE_BYTES;
        uint32_t sb = sa + 16384;

        #pragma unroll
        for (int kk = 0; kk < 4; ++kk) {
            uint32_t a[4][4], b[8][2];
            #pragma unroll
            for (int mf = 0; mf < 4; ++mf)
                ldsm_x4(a[mf], sa + sw128((aRow + mf * 16) * 128 + aCb + kk * 32));
            #pragma unroll
            for (int half = 0; half < 4; ++half) {
                uint32_t r[4];
                ldsm_x4(r, sb + sw128((bRow + half * 16) * 128 + bCb + kk * 32));
                b[2 * half][0] = r[0]; b[2 * half][1] = r[1];
                b[2 * half + 1][0] = r[2]; b[2 * half + 1][1] = r[3];
            }
            #pragma unroll
            for (int mf = 0; mf < 4; ++mf)
                #pragma unroll
                for (int nf = 0; nf < 8; ++nf)
                    mma16816(acc[mf][nf], a[mf], b[nf]);
        }
    }
    CP_WAIT0();

    // ---- epilogue: direct register -> gmem stores -----------------------------
    const int bb  = pxb >> 12;
    const int hw0 = pxb & 4095;
    const int oBase = o_tile * 128 + wm * 64 + (lane >> 2);
    const int nBase = hw0 + wn * 64 + (lane & 3) * 2;

    #pragma unroll
    for (int mf = 0; mf < 4; ++mf) {
        int o0 = oBase + mf * 16;
        float bz0 = __ldg(bias + o0);
        float bz8 = __ldg(bias + o0 + 8);
        float* op0 = out + (bb << 20) + (o0 << 12) + nBase;
        float* op8 = op0 + (8 << 12);
        #pragma unroll
        for (int nf = 0; nf < 8; ++nf) {
            float2 v0 = make_float2(acc[mf][nf][0] + bz0, acc[mf][nf][1] + bz0);
            float2 v1 = make_float2(acc[mf][nf][2] + bz8, acc[mf][nf][3] + bz8);
            *reinterpret_cast<float2*>(op0 + nf * 8) = v0;
            *reinterpret_cast<float2*>(op8 + nf * 8) = v1;
        }
    }
}

// ---------------- launch ------------------------------------------------------
extern "C" void kernel_launch(void* const* d_in, const int* in_sizes, int n_in,
                              void* d_out, int out_size) {
    const float* x      = (const float*)d_in[0];   // (4,256,64,64)
    const float* w_om   = (const float*)d_in[1];   // (27,256,3,3)
    const float* b_om   = (const float*)d_in[2];   // (27,)
    const float* weight = (const float*)d_in[3];   // (256,256,3,3)
    const float* bias   = (const float*)d_in[4];   // (256,)
    float* out = (float*)d_out;                    // (4,256,64,64)

    cudaFuncSetAttribute(offconv_kernel, cudaFuncAttributeMaxDynamicSharedMemorySize, SMEM2);
    cudaFuncSetAttribute(gemm_kernel, cudaFuncAttributeMaxDynamicSharedMemorySize, SMEM_DYN);

    prep_kernel<<<4960, 256>>>(x, w_om, weight);
    offconv_kernel<<<128, 256, SMEM2>>>();
    gather_kernel<<<2048, 256>>>(b_om);
    gemm_kernel<<<dim3(2, 128), 128, SMEM_DYN>>>(bias, out);
}

// round 16
// speedup vs baseline: 1.0426x; 1.0426x over previous
#include <cuda_runtime.h>
#include <cuda_bf16.h>
#include <cuda_fp16.h>
#include <math.h>
#include <cstdint>

// Problem constants
#define B   4
#define C   256
#define H   64
#define W   64
#define O   256
#define K   9           // 3x3
#define HW  4096        // H*W
#define CK  2304        // C*K
#define NPIX 16384      // B*H*W

// main GEMM config (1-pass fp16, occ 2) — R12 proven config
#define KC      64
#define NCHUNK  36      // 2304/64
#define STG     3
#define STAGE_BYTES 32768   // A 16KB + B 16KB
#define SMEM_DYN (1024 + STG * STAGE_BYTES)

// offset-conv GEMM config
#define NCH2    36      // 9 taps x 4 chunks of 64ch
#define STG2    4
#define STAGE2  20480   // A 4KB + B 16KB
#define SMEM2   (1024 + STG2 * STAGE2)

// ---------------- scratch (__device__ globals; no allocs allowed) -------------
__device__ float  g_om[B * 27 * HW];              // offset-conv output
__device__ __half g_xhalf[(size_t)NPIX * C];      // x in NHWC fp16 (offconv B + gather)
__device__ __half g_womh[32 * CK];                // w_om k-major fp16, rows 27..31 = 0
__device__ __half g_whalf[O * CK];                // weight k-major fp16
__device__ __half g_cols[(size_t)NPIX * CK];      // im2col cols fp16
__device__ __half g_zero[64];                     // zero-initialized OOB source

// ---------------- PTX helpers -------------------------------------------------
__device__ __forceinline__ uint32_t smem_u32(const void* p) {
    uint32_t a;
    asm("{ .reg .u64 t; cvta.to.shared.u64 t, %1; cvt.u32.u64 %0, t; }" : "=r"(a) : "l"(p));
    return a;
}
__device__ __forceinline__ void cp16(uint32_t dst, const void* src) {
    asm volatile("cp.async.cg.shared.global [%0], [%1], 16;" :: "r"(dst), "l"(src) : "memory");
}
#define CP_COMMIT() asm volatile("cp.async.commit_group;" ::: "memory")
#define CP_WAIT1()  asm volatile("cp.async.wait_group 1;" ::: "memory")
#define CP_WAIT2()  asm volatile("cp.async.wait_group 2;" ::: "memory")
#define CP_WAIT0()  asm volatile("cp.async.wait_group 0;" ::: "memory")

__device__ __forceinline__ uint32_t sw128(uint32_t off) { return off ^ ((off >> 3) & 0x70); }

__device__ __forceinline__ void ldsm_x4(uint32_t* r, uint32_t addr) {
    asm volatile("ldmatrix.sync.aligned.m8n8.x4.shared.b16 {%0,%1,%2,%3}, [%4];"
        : "=r"(r[0]), "=r"(r[1]), "=r"(r[2]), "=r"(r[3]) : "r"(addr));
}
__device__ __forceinline__ void mma16816(float* d, const uint32_t* a, const uint32_t* b) {
    asm volatile("mma.sync.aligned.m16n8k16.row.col.f32.f16.f16.f32 "
        "{%0,%1,%2,%3}, {%4,%5,%6,%7}, {%8,%9}, {%0,%1,%2,%3};"
        : "+f"(d[0]), "+f"(d[1]), "+f"(d[2]), "+f"(d[3])
        : "r"(a[0]), "r"(a[1]), "r"(a[2]), "r"(a[3]), "r"(b[0]), "r"(b[1]));
}

// ---------------- kernel 1: prep (transpose + wsplit + womprep) ----------------
// grid 2912 x 256 threads:
//   [0, 2048)    : NCHW->NHWC transpose (fp16, 64ch x 32px tiles, 128B stores)
//   [2048, 2624) : wsplit -> fp16 k-major
//   [2624, 2912) : w_om -> fp16 k-major padded to 32 rows
__global__ void __launch_bounds__(256) prep_kernel(const float* __restrict__ x,
                                                   const float* __restrict__ w_om,
                                                   const float* __restrict__ weight) {
    const int bid = blockIdx.x;
    const int tid = threadIdx.x;

    if (bid < 2048) {
        __shared__ float t[64][33];
        const int hw0 = (bid & 127) << 5;
        const int c0  = ((bid >> 7) & 3) << 6;
        const int b   = bid >> 9;
        const int tx = tid & 31, ty = tid >> 5;
        #pragma unroll
        for (int j = 0; j < 8; ++j) {
            int c = c0 + ty + 8 * j;
            t[ty + 8 * j][tx] = x[(((b << 8) + c) << 12) + hw0 + tx];
        }
        __syncthreads();
        uint32_t* xh32 = reinterpret_cast<uint32_t*>(g_xhalf);
        #pragma unroll
        for (int j = 0; j < 4; ++j) {
            int p = ty + 8 * j;
            __half2 v = __floats2half2_rn(t[2 * tx][p], t[2 * tx + 1][p]);
            xh32[(size_t)(((b << 12) + hw0 + p) << 7) + (c0 >> 1) + tx] =
                *reinterpret_cast<uint32_t*>(&v);
        }
    } else if (bid < 2624) {
        // ---- wsplit: fp16, k-major ----
        int i = (bid - 2048) * 1024 + tid * 4;  // < 589824
        const float4 v4 = *reinterpret_cast<const float4*>(weight + i);
        const float vs[4] = { v4.x, v4.y, v4.z, v4.w };
        #pragma unroll
        for (int q = 0; q < 4; ++q) {
            int e = i + q;
            int o = e / CK, r = e - o * CK;
            int c = r / 9, k = r - c * 9;
            g_whalf[o * CK + k * 256 + c] = __float2half_rn(vs[q]);
        }
    } else {
        // ---- womprep: womh[o][k*256+c] = w_om[o*2304 + c*9 + k], o<27 else 0 ----
        int i = (bid - 2624) * 256 + tid;       // < 73728 exactly
        int o = i / CK, r = i - o * CK;
        int k = r >> 8, c = r & 255;
        g_womh[i] = (o < 27) ? __float2half_rn(w_om[o * CK + c * 9 + k]) : __half(0.0f);
    }
}

// ---------------- kernel 2: offset-conv HMMA GEMM ------------------------------
// om[27, px] = w_om[27 x 2304] x im2col(x)[2304 x px].  B rows built on the fly
// from fp16 NHWC x: tap row = contiguous 64-ch chunk at shifted pixel (or zeros).
// grid 128 (one 128-px tile each), 256 threads (8 warps); warp tile 32(m) x 16(n).
__global__ void __launch_bounds__(256, 1)
offconv_kernel() {
    extern __shared__ __align__(16) char dyn_smem[];
    __shared__ int spx[K][128];                    // per-(tap, px) element offset or -1

    const uint32_t smem_base = smem_u32(dyn_smem);
    const uint32_t tile0 = (smem_base + 1023u) & ~1023u;

    const int tid  = threadIdx.x;
    const int wid  = tid >> 5;
    const int lane = tid & 31;
    const int pxb  = blockIdx.x << 7;              // 128 px per CTA
    const int b    = pxb >> 12;
    const int hwb  = pxb & 4095;

    // precompute per-px per-tap source offsets
    for (int i = tid; i < K * 128; i += 256) {
        int k = i >> 7, p = i & 127;
        int hw = hwb + p;
        int h = hw >> 6, w = hw & 63;
        int ky = k / 3 - 1, kx = k - (ky + 1) * 3 - 1;
        bool valid = ((unsigned)(h + ky) < H) && ((unsigned)(w + kx) < W);
        spx[k][p] = valid ? (((b << 12) + hw + ky * 64 + kx) << 8) : -1;
    }
    __syncthreads();

    const int rA = tid >> 3;      // 0..31
    const int sg = tid & 7;

    auto load_chunk = [&](int j) {
        int st = j % STG2;
        uint32_t sa = tile0 + st * STAGE2;         // A: 32 x 128B = 4KB
        uint32_t sb = sa + 4096;                   // B: 128 x 128B = 16KB
        int k  = j >> 2;
        int c0 = (j & 3) << 6;
        cp16(sa + sw128((uint32_t)(rA * 128 + sg * 16)), g_womh + rA * CK + k * 256 + c0 + sg * 8);
        #pragma unroll
        for (int q = 0; q < 4; ++q) {
            int idx = tid + (q << 8);
            int row = idx >> 3, s2 = idx & 7;
            int off = spx[k][row];
            const __half* src = (off >= 0) ? (g_xhalf + off + c0 + s2 * 8) : (g_zero + s2 * 8);
            cp16(sb + sw128((uint32_t)(row * 128 + s2 * 16)), src);
        }
        CP_COMMIT();
    };

    float acc[2][2][4];
    #pragma unroll
    for (int i = 0; i < 2; ++i)
        #pragma unroll
        for (int j = 0; j < 2; ++j)
            #pragma unroll
            for (int q = 0; q < 4; ++q) acc[i][j][q] = 0.0f;

    const uint32_t aRow = (uint32_t)(lane & 15);
    const uint32_t aCb  = (uint32_t)((lane >> 4) << 4);
    const uint32_t bRow = (uint32_t)(wid * 16 + ((lane >> 4) << 3) + (lane & 7));
    const uint32_t bCb  = (uint32_t)(((lane >> 3) & 1) << 4);

    load_chunk(0);
    load_chunk(1);
    load_chunk(2);

    for (int i = 0; i < NCH2; ++i) {
        CP_WAIT2();
        __syncthreads();
        if (i + STG2 - 1 < NCH2) load_chunk(i + STG2 - 1);

        int st = i % STG2;
        uint32_t sa = tile0 + st * STAGE2;
        uint32_t sb = sa + 4096;

        #pragma unroll
        for (int kk = 0; kk < 4; ++kk) {
            uint32_t a[2][4], bfr[2][2];
            #pragma unroll
            for (int mf = 0; mf < 2; ++mf)
                ldsm_x4(a[mf], sa + sw128((aRow + mf * 16) * 128 + aCb + kk * 32));
            {
                uint32_t r[4];
                ldsm_x4(r, sb + sw128(bRow * 128 + bCb + kk * 32));
                bfr[0][0] = r[0]; bfr[0][1] = r[1];
                bfr[1][0] = r[2]; bfr[1][1] = r[3];
            }
            #pragma unroll
            for (int mf = 0; mf < 2; ++mf)
                #pragma unroll
                for (int nf = 0; nf < 2; ++nf)
                    mma16816(acc[mf][nf], a[mf], bfr[nf]);
        }
    }
    CP_WAIT0();

    // epilogue: D[m=o][n=px] -> g_om[b][o][hw]
    const int nBase = hwb + wid * 16 + (lane & 3) * 2;
    #pragma unroll
    for (int mf = 0; mf < 2; ++mf) {
        int o0 = mf * 16 + (lane >> 2);
        int o8 = o0 + 8;
        #pragma unroll
        for (int nf = 0; nf < 2; ++nf) {
            int n = nBase + nf * 8;
            if (o0 < 27)
                *reinterpret_cast<float2*>(g_om + (b * 27 + o0) * HW + n) =
                    make_float2(acc[mf][nf][0], acc[mf][nf][1]);
            if (o8 < 27)
                *reinterpret_cast<float2*>(g_om + (b * 27 + o8) * HW + n) =
                    make_float2(acc[mf][nf][2], acc[mf][nf][3]);
        }
    }
}

// ---------------- kernel 3: fused params + gather (uint4, 8 ch/lane) -----------
// grid 2048, block 256 = 8 px. Phase 1: 72 threads compute the 8x9 sampling
// params into smem. Phase 2: warp = one pixel, lane = 8 channels, ONE iter/tap.
__global__ void __launch_bounds__(256) gather_kernel(const float* __restrict__ b_om) {
    __shared__ float4 s_ww[8][9];
    __shared__ int4   s_cc[8][9];

    const int tid  = threadIdx.x;
    const int pix0 = blockIdx.x << 3;
    const int b    = pix0 >> 12;

    if (tid < 72) {
        const int p = tid / 9;
        const int k = tid - p * 9;
        const int hw = (pix0 + p) & 4095;
        const int h  = hw >> 6;
        const int w  = hw & 63;
        const float* omb = g_om + b * 27 * HW + hw;

        float off_y = omb[(2 * k    ) * HW] + b_om[2 * k];
        float off_x = omb[(2 * k + 1) * HW] + b_om[2 * k + 1];
        float mval  = omb[(18 + k   ) * HW] + b_om[18 + k];
        float m = 1.0f / (1.0f + expf(-mval));

        float py = (float)(h - 1 + k / 3) + off_y;
        float px = (float)(w - 1 + k % 3) + off_x;

        float y0f = floorf(py), x0f = floorf(px);
        float ly = py - y0f, lx = px - x0f;
        int y0 = (int)y0f, x0 = (int)x0f;
        int y1 = y0 + 1,   x1 = x0 + 1;

        float vy0 = (y0 >= 0 && y0 < H) ? 1.0f : 0.0f;
        float vy1 = (y1 >= 0 && y1 < H) ? 1.0f : 0.0f;
        float vx0 = (x0 >= 0 && x0 < W) ? 1.0f : 0.0f;
        float vx1 = (x1 >= 0 && x1 < W) ? 1.0f : 0.0f;

        float4 wv;
        wv.x = (1.0f - ly) * (1.0f - lx) * m * vy0 * vx0;
        wv.y = (1.0f - ly) * lx          * m * vy0 * vx1;
        wv.z = ly * (1.0f - lx)          * m * vy1 * vx0;
        wv.w = ly * lx                   * m * vy1 * vx1;

        int4 cv;
        cv.x = min(max(y0, 0), H - 1) * W;
        cv.y = min(max(y1, 0), H - 1) * W;
        cv.z = min(max(x0, 0), W - 1);
        cv.w = min(max(x1, 0), W - 1);

        s_ww[p][k] = wv;
        s_cc[p][k] = cv;
    }
    __syncthreads();

    const int wid  = tid >> 5;
    const int lane = tid & 31;
    const int px   = pix0 + wid;

    // fp16 corners as uint4 = 8 halves; pixel stride = 256 halves = 32 uint4
    const uint4* xb = reinterpret_cast<const uint4*>(g_xhalf) + ((size_t)b << 17);
    uint4* outp = reinterpret_cast<uint4*>(g_cols + (size_t)px * CK);   // 288 uint4/px

    #pragma unroll
    for (int k = 0; k < K; ++k) {
        const float4 ww = s_ww[wid][k];
        const int4   cc = s_cc[wid][k];
        const int p00 = (cc.x + cc.z) << 5;
        const int p01 = (cc.x + cc.w) << 5;
        const int p10 = (cc.y + cc.z) << 5;
        const int p11 = (cc.y + cc.w) << 5;

        uint4 u00 = xb[p00 + lane];
        uint4 u01 = xb[p01 + lane];
        uint4 u10 = xb[p10 + lane];
        uint4 u11 = xb[p11 + lane];

        const uint32_t* a00 = &u00.x;
        const uint32_t* a01 = &u01.x;
        const uint32_t* a10 = &u10.x;
        const uint32_t* a11 = &u11.x;

        uint4 st;
        uint32_t* so = &st.x;
        #pragma unroll
        for (int q = 0; q < 4; ++q) {
            float2 f00 = __half22float2(*reinterpret_cast<const __half2*>(&a00[q]));
            float2 f01 = __half22float2(*reinterpret_cast<const __half2*>(&a01[q]));
            float2 f10 = __half22float2(*reinterpret_cast<const __half2*>(&a10[q]));
            float2 f11 = __half22float2(*reinterpret_cast<const __half2*>(&a11[q]));
            float va = ww.x * f00.x + ww.y * f01.x + ww.z * f10.x + ww.w * f11.x;
            float vb = ww.x * f00.y + ww.y * f01.y + ww.z * f10.y + ww.w * f11.y;
            __half2 h2 = __floats2half2_rn(va, vb);
            so[q] = *reinterpret_cast<uint32_t*>(&h2);
        }
        outp[k * 32 + lane] = st;
    }
}

// ---------------- kernel 4: HMMA GEMM  D[o, px] = Whalf x Cols^T ---------------
// grid (2, 128): tile 128(o) x 128(px), 256 CTAs, occupancy 2 (R12 config).
// 8 warps as 2(m) x 4(n); warp tile 64 x 32. 3-stage cp.async, K = 2304 fp16.
__global__ void __launch_bounds__(256, 2)
gemm_kernel(const float* __restrict__ bias, float* __restrict__ out) {
    extern __shared__ __align__(16) char dyn_smem[];
    const uint32_t smem_base = smem_u32(dyn_smem);
    const uint32_t tile0 = (smem_base + 1023u) & ~1023u;

    const int tid  = threadIdx.x;
    const int wid  = tid >> 5;
    const int lane = tid & 31;
    const int o_tile = blockIdx.x;            // 0..1 (fast dim: same-px pair adjacent)
    const int pxb    = blockIdx.y << 7;       // 128 px per CTA

    const int wm = wid & 1;                   // m offset 64*wm
    const int wn = wid >> 1;                  // n offset 32*wn

    const __half* wA = g_whalf + (size_t)o_tile * 128 * CK;
    const __half* cB = g_cols + (size_t)pxb * CK;

    const int r0 = tid >> 3;                  // 0..31
    const int sg = tid & 7;

    auto load_chunk = [&](int j) {
        int st = j % STG;
        uint32_t sa = tile0 + st * STAGE_BYTES;
        uint32_t sb = sa + 16384;
        int koff = j * KC + sg * 8;
        #pragma unroll
        for (int q = 0; q < 4; ++q) {        // A: 128 rows
            int r = r0 + (q << 5);
            cp16(sa + sw128((uint32_t)(r * 128 + sg * 16)), wA + (size_t)r * CK + koff);
        }
        #pragma unroll
        for (int q = 0; q < 4; ++q) {        // B: 128 rows
            int r = r0 + (q << 5);
            cp16(sb + sw128((uint32_t)(r * 128 + sg * 16)), cB + (size_t)r * CK + koff);
        }
        CP_COMMIT();
    };

    float acc[4][4][4];
    #pragma unroll
    for (int i = 0; i < 4; ++i)
        #pragma unroll
        for (int j = 0; j < 4; ++j)
            #pragma unroll
            for (int q = 0; q < 4; ++q) acc[i][j][q] = 0.0f;

    const uint32_t aRow = (uint32_t)(wm * 64 + (lane & 15));
    const uint32_t aCb  = (uint32_t)((lane >> 4) << 4);
    const uint32_t bRow = (uint32_t)(wn * 32 + ((lane >> 4) << 3) + (lane & 7));
    const uint32_t bCb  = (uint32_t)(((lane >> 3) & 1) << 4);

    load_chunk(0);
    load_chunk(1);

    for (int i = 0; i < NCHUNK; ++i) {
        if (i + 1 < NCHUNK) CP_WAIT1(); else CP_WAIT0();
        __syncthreads();
        if (i + STG - 1 < NCHUNK) load_chunk(i + STG - 1);

        int st = i % STG;
        uint32_t sa = tile0 + st * STAGE_BYTES;
        uint32_t sb = sa + 16384;

        #pragma unroll
        for (int kk = 0; kk < 4; ++kk) {
            uint32_t a[4][4], b[4][2];
            #pragma unroll
            for (int mf = 0; mf < 4; ++mf)
                ldsm_x4(a[mf], sa + sw128((aRow + mf * 16) * 128 + aCb + kk * 32));
            #pragma unroll
            for (int half = 0; half < 2; ++half) {
                uint32_t r[4];
                ldsm_x4(r, sb + sw128((bRow + half * 16) * 128 + bCb + kk * 32));
                b[2 * half][0] = r[0]; b[2 * half][1] = r[1];
                b[2 * half + 1][0] = r[2]; b[2 * half + 1][1] = r[3];
            }
            #pragma unroll
            for (int mf = 0; mf < 4; ++mf)
                #pragma unroll
                for (int nf = 0; nf < 4; ++nf)
                    mma16816(acc[mf][nf], a[mf], b[nf]);
        }
    }
    CP_WAIT0();

    // ---- epilogue: direct register -> gmem stores -----------------------------
    const int bb  = pxb >> 12;
    const int hw0 = pxb & 4095;
    const int oBase = o_tile * 128 + wm * 64 + (lane >> 2);
    const int nBase = hw0 + wn * 32 + (lane & 3) * 2;

    #pragma unroll
    for (int mf = 0; mf < 4; ++mf) {
        int o0 = oBase + mf * 16;
        float bz0 = __ldg(bias + o0);
        float bz8 = __ldg(bias + o0 + 8);
        float* op0 = out + (bb << 20) + (o0 << 12) + nBase;
        float* op8 = op0 + (8 << 12);
        #pragma unroll
        for (int nf = 0; nf < 4; ++nf) {
            float2 v0 = make_float2(acc[mf][nf][0] + bz0, acc[mf][nf][1] + bz0);
            float2 v1 = make_float2(acc[mf][nf][2] + bz8, acc[mf][nf][3] + bz8);
            *reinterpret_cast<float2*>(op0 + nf * 8) = v0;
            *reinterpret_cast<float2*>(op8 + nf * 8) = v1;
        }
    }
}

// ---------------- launch ------------------------------------------------------
extern "C" void kernel_launch(void* const* d_in, const int* in_sizes, int n_in,
                              void* d_out, int out_size) {
    const float* x      = (const float*)d_in[0];   // (4,256,64,64)
    const float* w_om   = (const float*)d_in[1];   // (27,256,3,3)
    const float* b_om   = (const float*)d_in[2];   // (27,)
    const float* weight = (const float*)d_in[3];   // (256,256,3,3)
    const float* bias   = (const float*)d_in[4];   // (256,)
    float* out = (float*)d_out;                    // (4,256,64,64)

    cudaFuncSetAttribute(offconv_kernel, cudaFuncAttributeMaxDynamicSharedMemorySize, SMEM2);
    cudaFuncSetAttribute(gemm_kernel, cudaFuncAttributeMaxDynamicSharedMemorySize, SMEM_DYN);

    prep_kernel<<<2912, 256>>>(x, w_om, weight);
    offconv_kernel<<<128, 256, SMEM2>>>();
    gather_kernel<<<2048, 256>>>(b_om);
    gemm_kernel<<<dim3(2, 128), 256, SMEM_DYN>>>(bias, out);
}